// round 7
// baseline (speedup 1.0000x reference)
#include <cuda_runtime.h>
#include <cuda_fp16.h>
#include <cstdint>

#define M_TOTAL 8192
#define N_TOTAL 11008
#define K_TOTAL 4096
#define GROUPS 32
#define PACKED 2048

// GEMM tiling: CTA 128x256x64, 16 warps (2M x 8N), warp tile 64x32, 4 stages.
#define BM 128
#define BN 256
#define BK 64
#define STAGES 4
#define NK_TILES (K_TOTAL / BK)   // 64

// SMEM: 128B rows (BK=64 halfs), XOR-swizzled, no padding.
#define A_BYTES (BM * 128)                 // 16384
#define B_BYTES (BN * 128)                 // 32768
#define STAGE_BYTES (A_BYTES + B_BYTES)    // 49152
#define SMEM_TOTAL (STAGES * STAGE_BYTES)  // 196608

// Scratch: dequantized W (fp16) and converted x (fp16).
__device__ __half g_W[(size_t)N_TOTAL * K_TOTAL];  // ~90 MB
__device__ __half g_X[(size_t)M_TOTAL * K_TOTAL];  // ~67 MB

__device__ __forceinline__ uint32_t smem_u32(const void* p) {
    uint32_t a;
    asm("{ .reg .u64 t; cvta.to.shared.u64 t, %1; cvt.u32.u64 %0, t; }"
        : "=r"(a) : "l"(p));
    return a;
}

__device__ __forceinline__ void cp_async16(uint32_t dst, const void* src) {
    asm volatile("cp.async.cg.shared.global [%0], [%1], 16;\n" :: "r"(dst), "l"(src));
}

__device__ __forceinline__ void ldsm_x4(uint32_t (&r)[4], uint32_t addr) {
    asm volatile("ldmatrix.sync.aligned.m8n8.x4.shared.b16 {%0,%1,%2,%3}, [%4];"
                 : "=r"(r[0]), "=r"(r[1]), "=r"(r[2]), "=r"(r[3]) : "r"(addr));
}

// ---------------------------------------------------------------------------
// Kernel 1: int4 grouped dequant -> fp16 (4 packed int32 / thread)
// ---------------------------------------------------------------------------
__global__ void dequant_kernel(const int4* __restrict__ wp4,
                               const float* __restrict__ scale,
                               const float* __restrict__ zp) {
    int c = blockIdx.x * blockDim.x + threadIdx.x;
    if (c >= N_TOTAL * (PACKED / 4)) return;
    int o = c >> 9;
    int pc = c & 511;
    int g = pc >> 4;
    float s = __ldg(scale + o * GROUPS + g);
    float z = __ldg(zp + o * GROUPS + g);
    int4 v = wp4[c];
    uint4 outv;
    __half2 h0 = __floats2half2_rn(((float)((v.x >> 4) & 15) - z) * s,
                                   ((float)(v.x & 15) - z) * s);
    __half2 h1 = __floats2half2_rn(((float)((v.y >> 4) & 15) - z) * s,
                                   ((float)(v.y & 15) - z) * s);
    __half2 h2 = __floats2half2_rn(((float)((v.z >> 4) & 15) - z) * s,
                                   ((float)(v.z & 15) - z) * s);
    __half2 h3 = __floats2half2_rn(((float)((v.w >> 4) & 15) - z) * s,
                                   ((float)(v.w & 15) - z) * s);
    outv.x = *(uint32_t*)&h0;
    outv.y = *(uint32_t*)&h1;
    outv.z = *(uint32_t*)&h2;
    outv.w = *(uint32_t*)&h3;
    reinterpret_cast<uint4*>(g_W)[c] = outv;
}

// ---------------------------------------------------------------------------
// Kernel 2: x fp32 -> fp16
// ---------------------------------------------------------------------------
__global__ void xconv_kernel(const float* __restrict__ x) {
    int i = blockIdx.x * blockDim.x + threadIdx.x;
    float4 f = reinterpret_cast<const float4*>(x)[i];
    __half2 h0 = __floats2half2_rn(f.x, f.y);
    __half2 h1 = __floats2half2_rn(f.z, f.w);
    uint2 o;
    o.x = *(uint32_t*)&h0;
    o.y = *(uint32_t*)&h1;
    reinterpret_cast<uint2*>(g_X)[i] = o;
}

// ---------------------------------------------------------------------------
// Kernel 3: GEMM  out[m][n] = sum_k X[m][k] * W[n][k] + bias[n]
// XOR swizzle within 128B rows: byte_in_row ^= (row & 7) << 4.
// One __syncthreads per K-tile; 4-stage cp.async, wait_group 2.
// ---------------------------------------------------------------------------
__global__ void __launch_bounds__(512, 1)
gemm_kernel(float* __restrict__ out, const float* __restrict__ bias) {
    extern __shared__ __half smem[];
    const uint32_t sb = smem_u32(smem);

    const int tid  = threadIdx.x;
    const int lane = tid & 31;
    const int warp = tid >> 5;
    const int wm = (warp & 1) * 64;   // 2 warps in M
    const int wn = (warp >> 1) * 32;  // 8 warps in N

    const int m0 = blockIdx.y * BM;
    const int n0 = blockIdx.x * BN;

    const __half* Ag = g_X + (size_t)m0 * K_TOTAL;
    const __half* Bg = g_W + (size_t)n0 * K_TOTAL;

    float acc[4][4][4];
#pragma unroll
    for (int mi = 0; mi < 4; mi++)
#pragma unroll
        for (int ni = 0; ni < 4; ni++)
#pragma unroll
            for (int e = 0; e < 4; e++) acc[mi][ni][e] = 0.0f;

    // Loader: A 1024 chunks, B 2048 chunks of 16B; 512 threads -> 2 + 4 each.
    auto load_stage = [&](int s, int k0) {
        const uint32_t base = sb + (uint32_t)s * STAGE_BYTES;
#pragma unroll
        for (int i = 0; i < 2; i++) {
            int c = tid + (i << 9);
            int row = c >> 3, seg = c & 7;
            uint32_t off = (uint32_t)(row * 128) +
                           (((uint32_t)(seg * 16)) ^ (((uint32_t)row & 7u) << 4));
            cp_async16(base + off, Ag + (size_t)row * K_TOTAL + k0 + seg * 8);
        }
#pragma unroll
        for (int i = 0; i < 4; i++) {
            int c = tid + (i << 9);
            int row = c >> 3, seg = c & 7;
            uint32_t off = (uint32_t)(row * 128) +
                           (((uint32_t)(seg * 16)) ^ (((uint32_t)row & 7u) << 4));
            cp_async16(base + (uint32_t)A_BYTES + off,
                       Bg + (size_t)row * K_TOTAL + k0 + seg * 8);
        }
        asm volatile("cp.async.commit_group;\n" ::: "memory");
    };

    // Prologue: stages 0..2.
    load_stage(0, 0);
    load_stage(1, BK);
    load_stage(2, 2 * BK);

    // Per-lane ldmatrix addressing: 16 rows (lane&15), byte col 16*(lane>>4).
    const int r16 = lane & 15;
    const uint32_t hi16 = (uint32_t)((lane >> 4) * 16);
    const uint32_t xorv = ((uint32_t)(r16 & 7)) << 4;
    uint32_t a_row[4], b_row[2];
#pragma unroll
    for (int mi = 0; mi < 4; mi++)
        a_row[mi] = (uint32_t)((wm + mi * 16 + r16) * 128);
#pragma unroll
    for (int ng = 0; ng < 2; ng++)
        b_row[ng] = (uint32_t)A_BYTES + (uint32_t)((wn + ng * 16 + r16) * 128);

    for (int i = 0; i < NK_TILES; i++) {
        // Pending groups: {i, i+1, i+2}. Wait until stage i is resident.
        asm volatile("cp.async.wait_group %0;\n" :: "n"(STAGES - 2) : "memory");
        __syncthreads();

        // Prefetch stage i+3 into slot (i+3)%4 (= (i-1)%4, whose readers all
        // passed the barrier above).
        if (i + STAGES - 1 < NK_TILES) {
            load_stage((i + STAGES - 1) % STAGES, (i + STAGES - 1) * BK);
        } else {
            asm volatile("cp.async.commit_group;\n" ::: "memory");
        }

        const uint32_t st = sb + (uint32_t)((i % STAGES) * STAGE_BYTES);
#pragma unroll
        for (int ks = 0; ks < BK; ks += 16) {
            const uint32_t colb = (((uint32_t)(ks * 2)) + hi16) ^ xorv;
            uint32_t a[4][4];
#pragma unroll
            for (int mi = 0; mi < 4; mi++)
                ldsm_x4(a[mi], st + a_row[mi] + colb);
            uint32_t b[4][2];
#pragma unroll
            for (int ng = 0; ng < 2; ng++) {
                uint32_t r[4];
                ldsm_x4(r, st + b_row[ng] + colb);
                b[ng * 2 + 0][0] = r[0]; b[ng * 2 + 0][1] = r[2];
                b[ng * 2 + 1][0] = r[1]; b[ng * 2 + 1][1] = r[3];
            }
#pragma unroll
            for (int mi = 0; mi < 4; mi++)
#pragma unroll
                for (int ni = 0; ni < 4; ni++) {
                    asm volatile(
                        "mma.sync.aligned.m16n8k16.row.col.f32.f16.f16.f32 "
                        "{%0,%1,%2,%3}, {%4,%5,%6,%7}, {%8,%9}, {%0,%1,%2,%3};\n"
                        : "+f"(acc[mi][ni][0]), "+f"(acc[mi][ni][1]),
                          "+f"(acc[mi][ni][2]), "+f"(acc[mi][ni][3])
                        : "r"(a[mi][0]), "r"(a[mi][1]), "r"(a[mi][2]), "r"(a[mi][3]),
                          "r"(b[ni][0]), "r"(b[ni][1]));
                }
        }
    }

    // Epilogue: bias + fp32 store.
    const int r  = lane >> 2;
    const int c2 = (lane & 3) * 2;
#pragma unroll
    for (int mi = 0; mi < 4; mi++) {
        const int row = m0 + wm + mi * 16 + r;
        float* o0 = out + (size_t)row * N_TOTAL + n0 + wn;
        float* o1 = o0 + (size_t)8 * N_TOTAL;
#pragma unroll
        for (int ni = 0; ni < 4; ni++) {
            const int col = ni * 8 + c2;
            const float b0 = __ldg(bias + n0 + wn + col);
            const float b1 = __ldg(bias + n0 + wn + col + 1);
            *reinterpret_cast<float2*>(o0 + col) =
                make_float2(acc[mi][ni][0] + b0, acc[mi][ni][1] + b1);
            *reinterpret_cast<float2*>(o1 + col) =
                make_float2(acc[mi][ni][2] + b0, acc[mi][ni][3] + b1);
        }
    }
}

// ---------------------------------------------------------------------------
// Launch
// ---------------------------------------------------------------------------
extern "C" void kernel_launch(void* const* d_in, const int* in_sizes, int n_in,
                              void* d_out, int out_size) {
    const float* x     = (const float*)d_in[0];
    const int*   wp    = (const int*)d_in[1];
    const float* scale = (const float*)d_in[2];
    const float* zp    = (const float*)d_in[3];
    const float* bias  = (const float*)d_in[4];
    float* out = (float*)d_out;

    dequant_kernel<<<(N_TOTAL * (PACKED / 4) + 255) / 256, 256>>>(
        (const int4*)wp, scale, zp);
    xconv_kernel<<<(M_TOTAL * K_TOTAL / 4) / 256, 256>>>(x);

    cudaFuncSetAttribute(gemm_kernel,
                         cudaFuncAttributeMaxDynamicSharedMemorySize, SMEM_TOTAL);
    dim3 grid(N_TOTAL / BN, M_TOTAL / BM);  // 43 x 64
    gemm_kernel<<<grid, 512, SMEM_TOTAL>>>(out, bias);
}

// round 8
// speedup vs baseline: 1.0993x; 1.0993x over previous
#include <cuda_runtime.h>
#include <cuda_fp16.h>
#include <cstdint>

#define M_TOTAL 8192
#define N_TOTAL 11008
#define K_TOTAL 4096
#define GROUPS 32
#define PACKED 2048

// GEMM tiling: CTA 128x128x64, 8 warps (2M x 4N), warp tile 64x32, 3 stages.
#define BM 128
#define BN 128
#define BK 64
#define STAGES 3
#define NK_TILES (K_TOTAL / BK)   // 64
#define TILES_N (N_TOTAL / BN)    // 86
#define TILES_M (M_TOTAL / BM)    // 64
#define GROUP_M 8

// SMEM: 128B rows (BK=64 halfs), XOR-swizzled, no padding.
#define A_BYTES (BM * 128)                 // 16384
#define B_BYTES (BN * 128)                 // 16384
#define STAGE_BYTES (A_BYTES + B_BYTES)    // 32768
#define SMEM_TOTAL (STAGES * STAGE_BYTES)  // 98304

// Scratch: dequantized W (fp16) and converted x (fp16).
__device__ __half g_W[(size_t)N_TOTAL * K_TOTAL];  // ~90 MB
__device__ __half g_X[(size_t)M_TOTAL * K_TOTAL];  // ~67 MB

__device__ __forceinline__ uint32_t smem_u32(const void* p) {
    uint32_t a;
    asm("{ .reg .u64 t; cvta.to.shared.u64 t, %1; cvt.u32.u64 %0, t; }"
        : "=r"(a) : "l"(p));
    return a;
}

__device__ __forceinline__ void cp_async16(uint32_t dst, const void* src) {
    asm volatile("cp.async.cg.shared.global [%0], [%1], 16;\n" :: "r"(dst), "l"(src));
}

__device__ __forceinline__ void ldsm_x4(uint32_t (&r)[4], uint32_t addr) {
    asm volatile("ldmatrix.sync.aligned.m8n8.x4.shared.b16 {%0,%1,%2,%3}, [%4];"
                 : "=r"(r[0]), "=r"(r[1]), "=r"(r[2]), "=r"(r[3]) : "r"(addr));
}

// ---------------------------------------------------------------------------
// Kernel 1: int4 grouped dequant -> fp16 (4 packed int32 / thread)
// ---------------------------------------------------------------------------
__global__ void dequant_kernel(const int4* __restrict__ wp4,
                               const float* __restrict__ scale,
                               const float* __restrict__ zp) {
    int c = blockIdx.x * blockDim.x + threadIdx.x;
    if (c >= N_TOTAL * (PACKED / 4)) return;
    int o = c >> 9;
    int pc = c & 511;
    int g = pc >> 4;
    float s = __ldg(scale + o * GROUPS + g);
    float z = __ldg(zp + o * GROUPS + g);
    int4 v = wp4[c];
    uint4 outv;
    __half2 h0 = __floats2half2_rn(((float)((v.x >> 4) & 15) - z) * s,
                                   ((float)(v.x & 15) - z) * s);
    __half2 h1 = __floats2half2_rn(((float)((v.y >> 4) & 15) - z) * s,
                                   ((float)(v.y & 15) - z) * s);
    __half2 h2 = __floats2half2_rn(((float)((v.z >> 4) & 15) - z) * s,
                                   ((float)(v.z & 15) - z) * s);
    __half2 h3 = __floats2half2_rn(((float)((v.w >> 4) & 15) - z) * s,
                                   ((float)(v.w & 15) - z) * s);
    outv.x = *(uint32_t*)&h0;
    outv.y = *(uint32_t*)&h1;
    outv.z = *(uint32_t*)&h2;
    outv.w = *(uint32_t*)&h3;
    reinterpret_cast<uint4*>(g_W)[c] = outv;
}

// ---------------------------------------------------------------------------
// Kernel 2: x fp32 -> fp16
// ---------------------------------------------------------------------------
__global__ void xconv_kernel(const float* __restrict__ x) {
    int i = blockIdx.x * blockDim.x + threadIdx.x;
    float4 f = reinterpret_cast<const float4*>(x)[i];
    __half2 h0 = __floats2half2_rn(f.x, f.y);
    __half2 h1 = __floats2half2_rn(f.z, f.w);
    uint2 o;
    o.x = *(uint32_t*)&h0;
    o.y = *(uint32_t*)&h1;
    reinterpret_cast<uint2*>(g_X)[i] = o;
}

// ---------------------------------------------------------------------------
// Kernel 3: GEMM  out[m][n] = sum_k X[m][k] * W[n][k] + bias[n]
// XOR swizzle within 128B rows: byte_in_row ^= (row & 7) << 4.
// Single __syncthreads per K-tile; supertile rasterization (8 M-rows, M-fast).
// ---------------------------------------------------------------------------
__global__ void __launch_bounds__(256, 2)
gemm_kernel(float* __restrict__ out, const float* __restrict__ bias) {
    extern __shared__ __half smem[];
    const uint32_t sb = smem_u32(smem);

    const int tid  = threadIdx.x;
    const int lane = tid & 31;
    const int warp = tid >> 5;
    const int wm = (warp & 1) * 64;
    const int wn = (warp >> 1) * 32;

    // Supertile raster: groups of GROUP_M m-tiles; within a group, m-fast.
    const int bid = blockIdx.x;
    const int group = bid / (TILES_N * GROUP_M);
    const int rem   = bid % (TILES_N * GROUP_M);
    const int m0 = (group * GROUP_M + (rem % GROUP_M)) * BM;
    const int n0 = (rem / GROUP_M) * BN;

    const __half* Ag = g_X + (size_t)m0 * K_TOTAL;
    const __half* Bg = g_W + (size_t)n0 * K_TOTAL;

    float acc[4][4][4];
#pragma unroll
    for (int mi = 0; mi < 4; mi++)
#pragma unroll
        for (int ni = 0; ni < 4; ni++)
#pragma unroll
            for (int e = 0; e < 4; e++) acc[mi][ni][e] = 0.0f;

    // Loader: 1024 chunks of 16B each for A and B; 256 threads -> 4+4 each.
    auto load_stage = [&](int s, int k0) {
        const uint32_t base = sb + (uint32_t)s * STAGE_BYTES;
#pragma unroll
        for (int i = 0; i < 4; i++) {
            int c = tid + (i << 8);
            int row = c >> 3, seg = c & 7;
            uint32_t off = (uint32_t)(row * 128) +
                           (((uint32_t)(seg * 16)) ^ (((uint32_t)row & 7u) << 4));
            cp_async16(base + off, Ag + (size_t)row * K_TOTAL + k0 + seg * 8);
        }
#pragma unroll
        for (int i = 0; i < 4; i++) {
            int c = tid + (i << 8);
            int row = c >> 3, seg = c & 7;
            uint32_t off = (uint32_t)(row * 128) +
                           (((uint32_t)(seg * 16)) ^ (((uint32_t)row & 7u) << 4));
            cp_async16(base + (uint32_t)A_BYTES + off,
                       Bg + (size_t)row * K_TOTAL + k0 + seg * 8);
        }
        asm volatile("cp.async.commit_group;\n" ::: "memory");
    };

    load_stage(0, 0);
    load_stage(1, BK);

    // Per-lane ldmatrix addressing.
    const int r16 = lane & 15;
    const uint32_t hi16 = (uint32_t)((lane >> 4) * 16);
    const uint32_t xorv = ((uint32_t)(r16 & 7)) << 4;
    uint32_t a_row[4], b_row[2];
#pragma unroll
    for (int mi = 0; mi < 4; mi++)
        a_row[mi] = (uint32_t)((wm + mi * 16 + r16) * 128);
#pragma unroll
    for (int ng = 0; ng < 2; ng++)
        b_row[ng] = (uint32_t)A_BYTES + (uint32_t)((wn + ng * 16 + r16) * 128);

    for (int i = 0; i < NK_TILES; i++) {
        asm volatile("cp.async.wait_group 1;\n" ::: "memory");
        __syncthreads();
        // All warps have finished reading slot (i+2)%3 (== (i-1)%3) before this
        // barrier, so prefetching into it now is safe without a second barrier.
        if (i + 2 < NK_TILES) {
            load_stage((i + 2) % STAGES, (i + 2) * BK);
        } else {
            asm volatile("cp.async.commit_group;\n" ::: "memory");
        }

        const uint32_t st = sb + (uint32_t)((i % STAGES) * STAGE_BYTES);
#pragma unroll
        for (int ks = 0; ks < BK; ks += 16) {
            const uint32_t colb = (((uint32_t)(ks * 2)) + hi16) ^ xorv;
            uint32_t a[4][4];
#pragma unroll
            for (int mi = 0; mi < 4; mi++)
                ldsm_x4(a[mi], st + a_row[mi] + colb);
            uint32_t b[4][2];
#pragma unroll
            for (int ng = 0; ng < 2; ng++) {
                uint32_t r[4];
                ldsm_x4(r, st + b_row[ng] + colb);
                b[ng * 2 + 0][0] = r[0]; b[ng * 2 + 0][1] = r[2];
                b[ng * 2 + 1][0] = r[1]; b[ng * 2 + 1][1] = r[3];
            }
#pragma unroll
            for (int mi = 0; mi < 4; mi++)
#pragma unroll
                for (int ni = 0; ni < 4; ni++) {
                    asm volatile(
                        "mma.sync.aligned.m16n8k16.row.col.f32.f16.f16.f32 "
                        "{%0,%1,%2,%3}, {%4,%5,%6,%7}, {%8,%9}, {%0,%1,%2,%3};\n"
                        : "+f"(acc[mi][ni][0]), "+f"(acc[mi][ni][1]),
                          "+f"(acc[mi][ni][2]), "+f"(acc[mi][ni][3])
                        : "r"(a[mi][0]), "r"(a[mi][1]), "r"(a[mi][2]), "r"(a[mi][3]),
                          "r"(b[ni][0]), "r"(b[ni][1]));
                }
        }
    }

    // Epilogue: bias + fp32 store.
    const int r  = lane >> 2;
    const int c2 = (lane & 3) * 2;
#pragma unroll
    for (int mi = 0; mi < 4; mi++) {
        const int row = m0 + wm + mi * 16 + r;
        float* o0 = out + (size_t)row * N_TOTAL + n0 + wn;
        float* o1 = o0 + (size_t)8 * N_TOTAL;
#pragma unroll
        for (int ni = 0; ni < 4; ni++) {
            const int col = ni * 8 + c2;
            const float b0 = __ldg(bias + n0 + wn + col);
            const float b1 = __ldg(bias + n0 + wn + col + 1);
            *reinterpret_cast<float2*>(o0 + col) =
                make_float2(acc[mi][ni][0] + b0, acc[mi][ni][1] + b1);
            *reinterpret_cast<float2*>(o1 + col) =
                make_float2(acc[mi][ni][2] + b0, acc[mi][ni][3] + b1);
        }
    }
}

// ---------------------------------------------------------------------------
// Launch
// ---------------------------------------------------------------------------
extern "C" void kernel_launch(void* const* d_in, const int* in_sizes, int n_in,
                              void* d_out, int out_size) {
    const float* x     = (const float*)d_in[0];
    const int*   wp    = (const int*)d_in[1];
    const float* scale = (const float*)d_in[2];
    const float* zp    = (const float*)d_in[3];
    const float* bias  = (const float*)d_in[4];
    float* out = (float*)d_out;

    dequant_kernel<<<(N_TOTAL * (PACKED / 4) + 255) / 256, 256>>>(
        (const int4*)wp, scale, zp);
    xconv_kernel<<<(M_TOTAL * K_TOTAL / 4) / 256, 256>>>(x);

    cudaFuncSetAttribute(gemm_kernel,
                         cudaFuncAttributeMaxDynamicSharedMemorySize, SMEM_TOTAL);
    gemm_kernel<<<TILES_N * TILES_M, 256, SMEM_TOTAL>>>(out, bias);
}

// round 9
// speedup vs baseline: 1.1044x; 1.0046x over previous
#include <cuda_runtime.h>
#include <cuda_fp16.h>
#include <cstdint>

#define M_TOTAL 8192
#define N_TOTAL 11008
#define K_TOTAL 4096
#define GROUPS 32
#define PACKED 2048

// GEMM tiling: CTA 128x128x64, 8 warps (2M x 4N), warp tile 64x32, 3 stages.
#define BM 128
#define BN 128
#define BK 64
#define STAGES 3
#define NK_TILES (K_TOTAL / BK)   // 64
#define TILES_N (N_TOTAL / BN)    // 86
#define TILES_M (M_TOTAL / BM)    // 64
#define GROUP_M 8

// SMEM: 128B rows (BK=64 halfs), XOR-swizzled, no padding.
#define A_BYTES (BM * 128)                 // 16384
#define B_BYTES (BN * 128)                 // 16384
#define STAGE_BYTES (A_BYTES + B_BYTES)    // 32768
#define SMEM_TOTAL (STAGES * STAGE_BYTES)  // 98304

// Scratch: dequantized W (fp16) and converted x (fp16).
__device__ __half g_W[(size_t)N_TOTAL * K_TOTAL];  // ~90 MB
__device__ __half g_X[(size_t)M_TOTAL * K_TOTAL];  // ~67 MB

__device__ __forceinline__ uint32_t smem_u32(const void* p) {
    uint32_t a;
    asm("{ .reg .u64 t; cvta.to.shared.u64 t, %1; cvt.u32.u64 %0, t; }"
        : "=r"(a) : "l"(p));
    return a;
}

__device__ __forceinline__ void cp_async16(uint32_t dst, const void* src) {
    asm volatile("cp.async.cg.shared.global [%0], [%1], 16;\n" :: "r"(dst), "l"(src));
}

__device__ __forceinline__ void ldsm_x4(uint32_t (&r)[4], uint32_t addr) {
    asm volatile("ldmatrix.sync.aligned.m8n8.x4.shared.b16 {%0,%1,%2,%3}, [%4];"
                 : "=r"(r[0]), "=r"(r[1]), "=r"(r[2]), "=r"(r[3]) : "r"(addr));
}

// ---------------------------------------------------------------------------
// Kernel 1: int4 grouped dequant -> fp16 (4 packed int32 / thread)
// ---------------------------------------------------------------------------
__global__ void dequant_kernel(const int4* __restrict__ wp4,
                               const float* __restrict__ scale,
                               const float* __restrict__ zp) {
    int c = blockIdx.x * blockDim.x + threadIdx.x;
    if (c >= N_TOTAL * (PACKED / 4)) return;
    int o = c >> 9;
    int pc = c & 511;
    int g = pc >> 4;
    float s = __ldg(scale + o * GROUPS + g);
    float z = __ldg(zp + o * GROUPS + g);
    int4 v = wp4[c];
    uint4 outv;
    __half2 h0 = __floats2half2_rn(((float)((v.x >> 4) & 15) - z) * s,
                                   ((float)(v.x & 15) - z) * s);
    __half2 h1 = __floats2half2_rn(((float)((v.y >> 4) & 15) - z) * s,
                                   ((float)(v.y & 15) - z) * s);
    __half2 h2 = __floats2half2_rn(((float)((v.z >> 4) & 15) - z) * s,
                                   ((float)(v.z & 15) - z) * s);
    __half2 h3 = __floats2half2_rn(((float)((v.w >> 4) & 15) - z) * s,
                                   ((float)(v.w & 15) - z) * s);
    outv.x = *(uint32_t*)&h0;
    outv.y = *(uint32_t*)&h1;
    outv.z = *(uint32_t*)&h2;
    outv.w = *(uint32_t*)&h3;
    reinterpret_cast<uint4*>(g_W)[c] = outv;
}

// ---------------------------------------------------------------------------
// Kernel 2: x fp32 -> fp16
// ---------------------------------------------------------------------------
__global__ void xconv_kernel(const float* __restrict__ x) {
    int i = blockIdx.x * blockDim.x + threadIdx.x;
    float4 f = reinterpret_cast<const float4*>(x)[i];
    __half2 h0 = __floats2half2_rn(f.x, f.y);
    __half2 h1 = __floats2half2_rn(f.z, f.w);
    uint2 o;
    o.x = *(uint32_t*)&h0;
    o.y = *(uint32_t*)&h1;
    reinterpret_cast<uint2*>(g_X)[i] = o;
}

// ---------------------------------------------------------------------------
// Kernel 3: GEMM  out[m][n] = sum_k X[m][k] * W[n][k] + bias[n]
// XOR swizzle within 128B rows: byte_in_row ^= (row & 7) << 4.
// Single __syncthreads per K-tile; per-warp ks rotation to spread LDSM bursts.
// ---------------------------------------------------------------------------
__global__ void __launch_bounds__(256, 2)
gemm_kernel(float* __restrict__ out, const float* __restrict__ bias) {
    extern __shared__ __half smem[];
    const uint32_t sb = smem_u32(smem);

    const int tid  = threadIdx.x;
    const int lane = tid & 31;
    const int warp = tid >> 5;
    const int wm = (warp & 1) * 64;
    const int wn = (warp >> 1) * 32;

    // Supertile raster: groups of GROUP_M m-tiles; within a group, m-fast.
    const int bid = blockIdx.x;
    const int group = bid / (TILES_N * GROUP_M);
    const int rem   = bid % (TILES_N * GROUP_M);
    const int m0 = (group * GROUP_M + (rem % GROUP_M)) * BM;
    const int n0 = (rem / GROUP_M) * BN;

    float acc[4][4][4];
#pragma unroll
    for (int mi = 0; mi < 4; mi++)
#pragma unroll
        for (int ni = 0; ni < 4; ni++)
#pragma unroll
            for (int e = 0; e < 4; e++) acc[mi][ni][e] = 0.0f;

    // Hoisted loader addressing: per-thread smem offsets + global sources.
    uint32_t s_off[4];
    const __half* a_src[4];
    const __half* b_src[4];
    {
        const __half* Ag = g_X + (size_t)m0 * K_TOTAL;
        const __half* Bg = g_W + (size_t)n0 * K_TOTAL;
#pragma unroll
        for (int i = 0; i < 4; i++) {
            int c = tid + (i << 8);
            int row = c >> 3, seg = c & 7;
            s_off[i] = (uint32_t)(row * 128) +
                       (((uint32_t)(seg * 16)) ^ (((uint32_t)row & 7u) << 4));
            a_src[i] = Ag + (size_t)row * K_TOTAL + seg * 8;
            b_src[i] = Bg + (size_t)row * K_TOTAL + seg * 8;
        }
    }

    auto load_stage = [&](int s, int k0) {
        const uint32_t base = sb + (uint32_t)s * STAGE_BYTES;
#pragma unroll
        for (int i = 0; i < 4; i++)
            cp_async16(base + s_off[i], a_src[i] + k0);
#pragma unroll
        for (int i = 0; i < 4; i++)
            cp_async16(base + (uint32_t)A_BYTES + s_off[i], b_src[i] + k0);
        asm volatile("cp.async.commit_group;\n" ::: "memory");
    };

    load_stage(0, 0);
    load_stage(1, BK);

    // Per-lane ldmatrix addressing.
    const int r16 = lane & 15;
    const uint32_t hi16 = (uint32_t)((lane >> 4) * 16);
    const uint32_t xorv = ((uint32_t)(r16 & 7)) << 4;
    uint32_t a_row[4], b_row[2];
#pragma unroll
    for (int mi = 0; mi < 4; mi++)
        a_row[mi] = (uint32_t)((wm + mi * 16 + r16) * 128);
#pragma unroll
    for (int ng = 0; ng < 2; ng++)
        b_row[ng] = (uint32_t)A_BYTES + (uint32_t)((wn + ng * 16 + r16) * 128);

    const uint32_t wrot = (uint32_t)(warp & 3);

    for (int i = 0; i < NK_TILES; i++) {
        asm volatile("cp.async.wait_group 1;\n" ::: "memory");
        __syncthreads();
        // Slot (i+2)%3 (== (i-1)%3) was fully consumed before the barrier.
        if (i + 2 < NK_TILES) {
            load_stage((i + 2) % STAGES, (i + 2) * BK);
        } else {
            asm volatile("cp.async.commit_group;\n" ::: "memory");
        }

        const uint32_t st = sb + (uint32_t)((i % STAGES) * STAGE_BYTES);
        // Rotate K16-chunk order per warp: spreads LDSM bursts across the
        // smem crossbar instead of all 16 warps hitting the same chunk at once.
#pragma unroll
        for (int j = 0; j < 4; j++) {
            const uint32_t ksb = ((j + wrot) & 3u) << 5;   // ks*2 bytes
            const uint32_t colb = (ksb + hi16) ^ xorv;
            uint32_t a[4][4];
#pragma unroll
            for (int mi = 0; mi < 4; mi++)
                ldsm_x4(a[mi], st + a_row[mi] + colb);
            uint32_t b[4][2];
#pragma unroll
            for (int ng = 0; ng < 2; ng++) {
                uint32_t r[4];
                ldsm_x4(r, st + b_row[ng] + colb);
                b[ng * 2 + 0][0] = r[0]; b[ng * 2 + 0][1] = r[2];
                b[ng * 2 + 1][0] = r[1]; b[ng * 2 + 1][1] = r[3];
            }
#pragma unroll
            for (int mi = 0; mi < 4; mi++)
#pragma unroll
                for (int ni = 0; ni < 4; ni++) {
                    asm volatile(
                        "mma.sync.aligned.m16n8k16.row.col.f32.f16.f16.f32 "
                        "{%0,%1,%2,%3}, {%4,%5,%6,%7}, {%8,%9}, {%0,%1,%2,%3};\n"
                        : "+f"(acc[mi][ni][0]), "+f"(acc[mi][ni][1]),
                          "+f"(acc[mi][ni][2]), "+f"(acc[mi][ni][3])
                        : "r"(a[mi][0]), "r"(a[mi][1]), "r"(a[mi][2]), "r"(a[mi][3]),
                          "r"(b[ni][0]), "r"(b[ni][1]));
                }
        }
    }

    // Epilogue: bias + fp32 store.
    const int r  = lane >> 2;
    const int c2 = (lane & 3) * 2;
#pragma unroll
    for (int mi = 0; mi < 4; mi++) {
        const int row = m0 + wm + mi * 16 + r;
        float* o0 = out + (size_t)row * N_TOTAL + n0 + wn;
        float* o1 = o0 + (size_t)8 * N_TOTAL;
#pragma unroll
        for (int ni = 0; ni < 4; ni++) {
            const int col = ni * 8 + c2;
            const float b0 = __ldg(bias + n0 + wn + col);
            const float b1 = __ldg(bias + n0 + wn + col + 1);
            *reinterpret_cast<float2*>(o0 + col) =
                make_float2(acc[mi][ni][0] + b0, acc[mi][ni][1] + b1);
            *reinterpret_cast<float2*>(o1 + col) =
                make_float2(acc[mi][ni][2] + b0, acc[mi][ni][3] + b1);
        }
    }
}

// ---------------------------------------------------------------------------
// Launch
// ---------------------------------------------------------------------------
extern "C" void kernel_launch(void* const* d_in, const int* in_sizes, int n_in,
                              void* d_out, int out_size) {
    const float* x     = (const float*)d_in[0];
    const int*   wp    = (const int*)d_in[1];
    const float* scale = (const float*)d_in[2];
    const float* zp    = (const float*)d_in[3];
    const float* bias  = (const float*)d_in[4];
    float* out = (float*)d_out;

    dequant_kernel<<<(N_TOTAL * (PACKED / 4) + 255) / 256, 256>>>(
        (const int4*)wp, scale, zp);
    xconv_kernel<<<(M_TOTAL * K_TOTAL / 4) / 256, 256>>>(x);

    cudaFuncSetAttribute(gemm_kernel,
                         cudaFuncAttributeMaxDynamicSharedMemorySize, SMEM_TOTAL);
    gemm_kernel<<<TILES_N * TILES_M, 256, SMEM_TOTAL>>>(out, bias);
}